// round 1
// baseline (speedup 1.0000x reference)
#include <cuda_runtime.h>
#include <cstddef>

// Problem constants
#define IMG_H 512
#define IMG_W 512
#define NC    3
#define TILE_W 32
#define TILE_H 16
#define HALO_W (TILE_W + 2)   // 34
#define HALO_H (TILE_H + 2)   // 18

__constant__ float c_w[81];   // [ky][kx][ci][co] HWIO
__constant__ float c_b[3];

__global__ __launch_bounds__(256)
void patchenc_conv_pe_kernel(const float* __restrict__ X,
                             const float* __restrict__ pos_emb,
                             float* __restrict__ out)
{
    __shared__ float4 s[HALO_H * HALO_W];   // channel-padded tile (x,y,z used)

    const int b  = blockIdx.z;
    const int h0 = blockIdx.y * TILE_H;
    const int w0 = blockIdx.x * TILE_W;
    const float* __restrict__ Xb = X + (size_t)b * (IMG_H * IMG_W * NC);

    // ---- cooperative tile load with SAME zero-padding ----
    for (int p = threadIdx.x; p < HALO_H * HALO_W; p += 256) {
        int r = p / HALO_W;
        int x = p - r * HALO_W;
        int gh = h0 - 1 + r;
        int gw = w0 - 1 + x;
        float4 v = make_float4(0.f, 0.f, 0.f, 0.f);
        if ((unsigned)gh < (unsigned)IMG_H && (unsigned)gw < (unsigned)IMG_W) {
            const float* pp = Xb + ((size_t)gh * IMG_W + gw) * NC;
            v.x = pp[0]; v.y = pp[1]; v.z = pp[2];
        }
        s[p] = v;
    }
    __syncthreads();

    // ---- each thread: one x, two vertically adjacent pixels ----
    const int tx = threadIdx.x & 31;        // 0..31 -> tile x
    const int ty = threadIdx.x >> 5;        // 0..7
    const int lh = ty * 2;                  // tile y of first pixel (0..14)

    // register window: smem rows lh..lh+3, cols tx..tx+2
    float4 v[4][3];
#pragma unroll
    for (int rr = 0; rr < 4; rr++)
#pragma unroll
        for (int dx = 0; dx < 3; dx++)
            v[rr][dx] = s[(lh + rr) * HALO_W + tx + dx];

    float a00 = c_b[0], a01 = c_b[1], a02 = c_b[2];   // pixel (lh)
    float a10 = c_b[0], a11 = c_b[1], a12 = c_b[2];   // pixel (lh+1)

#pragma unroll
    for (int dy = 0; dy < 3; dy++) {
#pragma unroll
        for (int dx = 0; dx < 3; dx++) {
#pragma unroll
            for (int ci = 0; ci < 3; ci++) {
                float vv0 = (ci == 0) ? v[dy][dx].x     : (ci == 1) ? v[dy][dx].y     : v[dy][dx].z;
                float vv1 = (ci == 0) ? v[dy + 1][dx].x : (ci == 1) ? v[dy + 1][dx].y : v[dy + 1][dx].z;
                const int wb = ((dy * 3 + dx) * 3 + ci) * 3;
                float w0c = c_w[wb + 0];
                float w1c = c_w[wb + 1];
                float w2c = c_w[wb + 2];
                a00 += vv0 * w0c;  a01 += vv0 * w1c;  a02 += vv0 * w2c;
                a10 += vv1 * w0c;  a11 += vv1 * w1c;  a12 += vv1 * w2c;
            }
        }
    }

    // ---- PE add + permuted store (fine-patch PE, coarse-patch output) ----
    const int gw = w0 + tx;
    const size_t out_b = (size_t)b * (1024 * 768);

#pragma unroll
    for (int k = 0; k < 2; k++) {
        const int gh = h0 + lh + k;
        const int nf  = (gh >> 2) * 128 + (gw >> 2);
        const int pof = (gh & 3) * 12 + (gw & 3) * 3;
        const float* pe = pos_emb + nf * 48 + pof;
        const int np  = (gh >> 4) * 32 + (gw >> 4);
        float* o = out + out_b + (size_t)np * 768 + (gh & 15) * 48 + (gw & 15) * 3;
        if (k == 0) {
            o[0] = a00 + pe[0];
            o[1] = a01 + pe[1];
            o[2] = a02 + pe[2];
        } else {
            o[0] = a10 + pe[0];
            o[1] = a11 + pe[1];
            o[2] = a12 + pe[2];
        }
    }
}

extern "C" void kernel_launch(void* const* d_in, const int* in_sizes, int n_in,
                              void* d_out, int out_size)
{
    const float* X  = (const float*)d_in[0];
    const float* Kw = (const float*)d_in[1];   // 81 floats, HWIO
    const float* Bb = (const float*)d_in[2];   // 3 floats
    const float* PE = (const float*)d_in[3];   // 16384 x 48

    // weights+bias -> constant bank (D2D async memcpy: graph-capturable)
    cudaMemcpyToSymbolAsync(c_w, Kw, 81 * sizeof(float), 0, cudaMemcpyDeviceToDevice, 0);
    cudaMemcpyToSymbolAsync(c_b, Bb, 3 * sizeof(float), 0, cudaMemcpyDeviceToDevice, 0);

    dim3 grid(IMG_W / TILE_W, IMG_H / TILE_H, 32);
    patchenc_conv_pe_kernel<<<grid, 256>>>(X, PE, (float*)d_out);
}